// round 8
// baseline (speedup 1.0000x reference)
#include <cuda_runtime.h>
#include <cuda_fp16.h>
#include <cstdint>

#define MAPSZ 67108864u
typedef unsigned uint;
typedef unsigned long long u64;

// ---------------- device scratch: single fp16 planes ----------------
__device__ __half g_q16[4194304];     // q * 0.125, [b][t][h][d]
__device__ __half g_k16[4194304];     // k,        [b][t][h][d]
__device__ __half g_pq16[8388608];    // phi_q,    [bh][t][128]
__device__ __half g_pk16[8388608];    // phi_k,    [bh][t][128]
__device__ float  g_sk[64 * 128];     // column sums of phi_k per bh

// ---------------- helpers ----------------
__device__ __forceinline__ float frcp(float x) { float r; asm("rcp.approx.ftz.f32 %0,%1;" : "=f"(r) : "f"(x)); return r; }
__device__ __forceinline__ uint packh(float hi, float lo) { uint r; asm("cvt.rn.f16x2.f32 %0,%1,%2;" : "=r"(r) : "f"(hi), "f"(lo)); return r; }
__device__ __forceinline__ uint smem_u32(const void* p) {
    uint a; asm("{ .reg .u64 t; cvta.to.shared.u64 t,%1; cvt.u32.u64 %0,t; }" : "=r"(a) : "l"(p)); return a;
}
__device__ __forceinline__ void cp16(uint dst, const void* src) {
    asm volatile("cp.async.cg.shared.global [%0],[%1],16;" :: "r"(dst), "l"(src));
}
#define CP_COMMIT() asm volatile("cp.async.commit_group;")
#define CP_WAIT0()  asm volatile("cp.async.wait_group 0;")
#define CP_WAIT1()  asm volatile("cp.async.wait_group 1;")

__device__ __forceinline__ void ldsm4(uint* r, uint addr) {
    asm volatile("ldmatrix.sync.aligned.m8n8.x4.shared.b16 {%0,%1,%2,%3},[%4];"
                 : "=r"(r[0]), "=r"(r[1]), "=r"(r[2]), "=r"(r[3]) : "r"(addr));
}
__device__ __forceinline__ void mma168(float* c, const uint* a, uint b0, uint b1) {
    asm volatile("mma.sync.aligned.m16n8k16.row.col.f32.f16.f16.f32 "
                 "{%0,%1,%2,%3},{%4,%5,%6,%7},{%8,%9},{%0,%1,%2,%3};"
                 : "+f"(c[0]), "+f"(c[1]), "+f"(c[2]), "+f"(c[3])
                 : "r"(a[0]), "r"(a[1]), "r"(a[2]), "r"(a[3]), "r"(b0), "r"(b1));
}
__device__ __forceinline__ void stcs4(float* p, float4 v) {
    asm volatile("st.global.cs.v4.f32 [%0],{%1,%2,%3,%4};"
                 :: "l"(p), "f"(v.x), "f"(v.y), "f"(v.z), "f"(v.w) : "memory");
}

// =====================================================================
// Kernel 1: feature maps via hi/lo fp16 mma. grid 1024; 256 threads.
// =====================================================================
#define PXH 0u
#define PXL 18432u
#define PWH 36864u
#define PWL 46080u
#define PREP_SMEM 55296

__global__ __launch_bounds__(256) void hedgehog_prep3(
    const float* __restrict__ q, const float* __restrict__ k,
    const float* __restrict__ Wq, const float* __restrict__ bq,
    const float* __restrict__ Wk, const float* __restrict__ bk)
{
    extern __shared__ __align__(16) char sm[];
    const uint sb = smem_u32(sm);
    const int tid = threadIdx.x, bid = blockIdx.x;
    const int w = tid >> 5, l = tid & 31;
    const int tensor = bid >> 9, rem = bid & 511;
    const int b = rem >> 7, h = (rem >> 3) & 15, t0 = (rem & 7) * 128;
    const float* W  = tensor ? Wk : Wq;
    const float* bi = tensor ? bk : bq;
    const float* x  = tensor ? k  : q;
    const float sc  = tensor ? 1.0f : 0.125f;
    __half* xout = tensor ? g_k16 : g_q16;
    __half* pout = tensor ? g_pk16 : g_pq16;

    #pragma unroll
    for (int i = 0; i < 16; ++i) {
        int idx = i * 256 + tid;
        int e = idx >> 6, d = idx & 63;
        float v = W[idx];
        __half hv = __float2half_rn(v);
        *(__half*)(sm + PWH + (e * 72 + d) * 2) = hv;
        *(__half*)(sm + PWL + (e * 72 + d) * 2) = __float2half_rn(v - __half2float(hv));
    }
    {
        const int row = tid >> 1, hf = tid & 1;
        const size_t xi = ((size_t)((b * 1024 + t0 + row) * 16 + h)) * 64 + hf * 32;
        const float4* xp = (const float4*)(x + xi);
        uint* xw = (uint*)(xout + xi);
        uint* XH = (uint*)(sm + PXH + (row * 72 + hf * 32) * 2);
        uint* XL = (uint*)(sm + PXL + (row * 72 + hf * 32) * 2);
        #pragma unroll
        for (int i = 0; i < 8; ++i) {
            float4 v = xp[i];
            xw[i * 2]     = packh(v.y * sc, v.x * sc);
            xw[i * 2 + 1] = packh(v.w * sc, v.z * sc);
            uint h0 = packh(v.y, v.x), h1 = packh(v.w, v.z);
            XH[i * 2] = h0; XH[i * 2 + 1] = h1;
            float2 r0 = __half22float2(*(__half2*)&h0), r1 = __half22float2(*(__half2*)&h1);
            XL[i * 2]     = packh(v.y - r0.y, v.x - r0.x);
            XL[i * 2 + 1] = packh(v.w - r1.y, v.z - r1.x);
        }
    }
    __syncthreads();

    const uint aK  = (uint)(l >> 4) * 16;
    const uint aH  = sb + PXH + (w * 16 + (l & 15)) * 144u + aK;
    const uint aL  = sb + PXL + (w * 16 + (l & 15)) * 144u + aK;
    const uint bRow = (uint)((l & 7) + ((l >> 3) & 1) * 8);

    float acc[8][4];
    #pragma unroll
    for (int nj = 0; nj < 8; ++nj)
        #pragma unroll
        for (int e = 0; e < 4; ++e) acc[nj][e] = 0.f;

    #pragma unroll
    for (int ks = 0; ks < 4; ++ks) {
        uint AH[4], AL[4];
        ldsm4(AH, aH + ks * 32);
        ldsm4(AL, aL + ks * 32);
        #pragma unroll
        for (int g = 0; g < 4; ++g) {
            uint BH[4], BL[4];
            const uint bo = (g * 16 + bRow) * 144u + aK + ks * 32;
            ldsm4(BH, sb + PWH + bo);
            ldsm4(BL, sb + PWL + bo);
            mma168(acc[g * 2],     AH, BH[0], BH[2]);
            mma168(acc[g * 2],     AL, BH[0], BH[2]);
            mma168(acc[g * 2],     AH, BL[0], BL[2]);
            mma168(acc[g * 2 + 1], AH, BH[1], BH[3]);
            mma168(acc[g * 2 + 1], AL, BH[1], BH[3]);
            mma168(acc[g * 2 + 1], AH, BL[1], BL[3]);
        }
    }

    const float* bb = bi;
    const int r0 = w * 16 + (l >> 2), r1 = r0 + 8;
    uint* p0 = (uint*)(pout + ((size_t)(b * 16 + h) * 1024 + t0 + r0) * 128);
    uint* p1 = (uint*)(pout + ((size_t)(b * 16 + h) * 1024 + t0 + r1) * 128);
    #pragma unroll
    for (int nj = 0; nj < 8; ++nj) {
        const int c = nj * 8 + (l & 3) * 2;
        const float b0 = bb[c], b1 = bb[c + 1];
        float e0 = __expf(acc[nj][0] + b0), e1 = __expf(acc[nj][1] + b1);
        float e2 = __expf(acc[nj][2] + b0), e3 = __expf(acc[nj][3] + b1);
        const int ci = nj * 4 + (l & 3);
        p0[ci]      = packh(e1, e0);
        p0[32 + ci] = packh(frcp(e1), frcp(e0));
        p1[ci]      = packh(e3, e2);
        p1[32 + ci] = packh(frcp(e3), frcp(e2));
    }
}

// =====================================================================
// Kernel 1b: column sums of phi_k. grid 64 (one per bh), 256 threads.
// Coalesced half2 row sweeps.
// =====================================================================
__global__ __launch_bounds__(256) void hedgehog_ksum() {
    __shared__ float red[4][128];
    const int bh = blockIdx.x, tid = threadIdx.x;
    const int c2 = tid & 63, rg = tid >> 6;
    const __half2* src = (const __half2*)(g_pk16 + (size_t)bh * 131072) + c2;
    float sx = 0.f, sy = 0.f;
    #pragma unroll 8
    for (int t = rg; t < 1024; t += 4) {
        float2 v = __half22float2(src[(size_t)t * 64]);
        sx += v.x; sy += v.y;
    }
    red[rg][2 * c2] = sx; red[rg][2 * c2 + 1] = sy;
    __syncthreads();
    if (tid < 128)
        g_sk[bh * 128 + tid] = (red[0][tid] + red[1][tid]) + (red[2][tid] + red[3][tid]);
}

// =====================================================================
// Kernel 2: fp16 mma.sync main with coalesced staged stores.
// grid (8,64), 512 threads (16 warps 4x4).
// =====================================================================
#define QOFF  0u
#define PQOFF 18432u
#define B0OFF 53248u
#define BSZ   53248u
#define SKOFF 159744u
#define IVOFF 160256u
#define RSOFF 160768u
#define TSOFF 161280u          // 16 warps x 2304 B staging
#define SMEMB 198144

template<bool WITH_PK>
__device__ __forceinline__ void stageB(uint sb, uint bufo, int b, int h, int bh, int kr, int tid) {
    #pragma unroll
    for (int i = 0; i < 2; ++i) {
        int idx = i * 512 + tid;
        int r = idx >> 3, c = idx & 7;
        cp16(sb + bufo + r * 144u + c * 16u,
             g_k16 + ((size_t)((b * 1024 + kr + r) * 16 + h)) * 64 + c * 8);
    }
    if (WITH_PK) {
        #pragma unroll
        for (int i = 0; i < 4; ++i) {
            int idx = i * 512 + tid;
            int r = idx >> 4, c = idx & 15;
            cp16(sb + bufo + 18432u + r * 272u + c * 16u,
                 g_pk16 + ((size_t)bh * 1024 + kr + r) * 128 + c * 8);
        }
    }
}

// staged coalesced store of one 16x32 fragment tile (per warp).
// vals[nj][e] already final. orow0 = global ptr to (tile row 0, col of this warp&kt).
__device__ __forceinline__ void tile_store(float* stg, const float v[4][4], float* orow0, int l) {
    const int s0 = l >> 2, s1 = s0 + 8;
    #pragma unroll
    for (int nj = 0; nj < 4; ++nj) {
        uint c0 = ((uint)nj ^ (uint)(s0 & 3)) * 8 + 2 * (l & 3);
        uint c1 = ((uint)nj ^ (uint)(s1 & 3)) * 8 + 2 * (l & 3);
        *(float2*)(stg + s0 * 36 + c0) = make_float2(v[nj][0], v[nj][1]);
        *(float2*)(stg + s1 * 36 + c1) = make_float2(v[nj][2], v[nj][3]);
    }
    __syncwarp();
    #pragma unroll
    for (int j = 0; j < 4; ++j) {
        int srow = j * 4 + (l >> 3);
        uint ch = (uint)((l & 7) >> 1) ^ (uint)(srow & 3);
        float4 val = *(float4*)(stg + srow * 36 + ch * 8 + (l & 1) * 4);
        stcs4(orow0 + (size_t)srow * 16384 + (l & 7) * 4, val);
    }
    __syncwarp();
}

__global__ __launch_bounds__(512, 1) void hedgehog_main(float* __restrict__ out)
{
    extern __shared__ __align__(16) char sm[];
    const uint sb = smem_u32(sm);
    const int tid = threadIdx.x, w = tid >> 5, l = tid & 31;
    const int wr = w >> 2, wc = w & 3;
    const int qt = blockIdx.x, bh = blockIdx.y;
    const int b = bh >> 4, h = bh & 15, t0 = qt * 128;
    float* skf = (float*)(sm + SKOFF);
    float* ivf = (float*)(sm + IVOFF);
    float* rsf = (float*)(sm + RSOFF);
    float* stg = (float*)(sm + TSOFF) + w * 576;

    #pragma unroll
    for (int i = 0; i < 2; ++i) {
        int idx = i * 512 + tid;
        int r = idx >> 3, c = idx & 7;
        cp16(sb + QOFF + r * 144u + c * 16u,
             g_q16 + ((size_t)((b * 1024 + t0 + r) * 16 + h)) * 64 + c * 8);
    }
    #pragma unroll
    for (int i = 0; i < 4; ++i) {
        int idx = i * 512 + tid;
        int r = idx >> 4, c = idx & 15;
        cp16(sb + PQOFF + r * 272u + c * 16u,
             g_pq16 + ((size_t)bh * 1024 + t0 + r) * 128 + c * 8);
    }
    stageB<true>(sb, B0OFF, b, h, bh, 0, tid);
    CP_COMMIT();

    if (tid < 128) { skf[tid] = g_sk[bh * 128 + tid]; rsf[tid] = 0.f; }
    CP_WAIT0();
    __syncthreads();

    if (tid < 128) {
        const uint* pr = (const uint*)(sm + PQOFF + tid * 272);
        float s = 0.f;
        #pragma unroll 16
        for (int i = 0; i < 64; ++i) {
            float2 v = __half22float2(*(const __half2*)(pr + i));
            s = fmaf(v.x, skf[2 * i], s);
            s = fmaf(v.y, skf[2 * i + 1], s);
        }
        ivf[tid] = 1.0f / s;
    }
    __syncthreads();

    const uint aK = (uint)(l >> 4) * 16;
    const uint qA = sb + QOFF  + (wr * 32 + (l & 15)) * 144u + aK;
    const uint pA = sb + PQOFF + (wr * 32 + (l & 15)) * 272u + aK;
    const uint bRow = (uint)((l & 7) + ((l >> 3) & 1) * 8);
    const uint kBrel = (wc * 32 + bRow) * 144u + aK;
    const uint pBrel = (wc * 32 + bRow) * 272u + aK + 18432u;

    // warp-tile output base (row = t0+wr*32, col = wc*32)
    float* o1w = out + ((size_t)((b * 1024 + t0 + wr * 32) * 16 + h)) * 1024 + wc * 32;
    float* o2w = o1w + MAPSZ;

    float iv0[2], iv1[2];
    #pragma unroll
    for (int mi = 0; mi < 2; ++mi) {
        iv0[mi] = ivf[wr * 32 + mi * 16 + (l >> 2)];
        iv1[mi] = ivf[wr * 32 + mi * 16 + (l >> 2) + 8];
    }
    float rlo[2] = {0.f, 0.f}, rhi[2] = {0.f, 0.f};

    // ================= sweep 1 =================
    for (int kt = 0; kt < 8; ++kt) {
        if (kt < 7) { stageB<true>(sb, B0OFF + ((kt + 1) & 1) * BSZ, b, h, bh, (kt + 1) * 128, tid); CP_COMMIT(); CP_WAIT1(); }
        else CP_WAIT0();
        __syncthreads();
        const uint bufo = B0OFF + (kt & 1) * BSZ;

        float acc[2][4][4];
        #pragma unroll
        for (int mi = 0; mi < 2; ++mi)
            #pragma unroll
            for (int nj = 0; nj < 4; ++nj)
                #pragma unroll
                for (int e = 0; e < 4; ++e) acc[mi][nj][e] = 0.f;
        #pragma unroll
        for (int ks = 0; ks < 4; ++ks) {
            uint A0[4], A1[4], B0[4], B1[4];
            ldsm4(A0, qA + ks * 32);
            ldsm4(A1, qA + 2304 + ks * 32);
            ldsm4(B0, sb + bufo + kBrel + ks * 32);
            ldsm4(B1, sb + bufo + kBrel + 2304 + ks * 32);
            mma168(acc[0][0], A0, B0[0], B0[2]); mma168(acc[0][1], A0, B0[1], B0[3]);
            mma168(acc[0][2], A0, B1[0], B1[2]); mma168(acc[0][3], A0, B1[1], B1[3]);
            mma168(acc[1][0], A1, B0[0], B0[2]); mma168(acc[1][1], A1, B0[1], B0[3]);
            mma168(acc[1][2], A1, B1[0], B1[2]); mma168(acc[1][3], A1, B1[1], B1[3]);
        }
        #pragma unroll
        for (int mi = 0; mi < 2; ++mi)
            #pragma unroll
            for (int nj = 0; nj < 4; ++nj) {
                rlo[mi] += __expf(acc[mi][nj][0]) + __expf(acc[mi][nj][1]);
                rhi[mi] += __expf(acc[mi][nj][2]) + __expf(acc[mi][nj][3]);
            }

        #pragma unroll
        for (int mi = 0; mi < 2; ++mi)
            #pragma unroll
            for (int nj = 0; nj < 4; ++nj)
                #pragma unroll
                for (int e = 0; e < 4; ++e) acc[mi][nj][e] = 0.f;
        #pragma unroll
        for (int ks = 0; ks < 8; ++ks) {
            uint A0[4], A1[4], B0[4], B1[4];
            ldsm4(A0, pA + ks * 32);
            ldsm4(A1, pA + 4352 + ks * 32);
            ldsm4(B0, sb + bufo + pBrel + ks * 32);
            ldsm4(B1, sb + bufo + pBrel + 4352 + ks * 32);
            mma168(acc[0][0], A0, B0[0], B0[2]); mma168(acc[0][1], A0, B0[1], B0[3]);
            mma168(acc[0][2], A0, B1[0], B1[2]); mma168(acc[0][3], A0, B1[1], B1[3]);
            mma168(acc[1][0], A1, B0[0], B0[2]); mma168(acc[1][1], A1, B0[1], B0[3]);
            mma168(acc[1][2], A1, B1[0], B1[2]); mma168(acc[1][3], A1, B1[1], B1[3]);
        }
        #pragma unroll
        for (int mi = 0; mi < 2; ++mi) {
            float v[4][4];
            #pragma unroll
            for (int nj = 0; nj < 4; ++nj) {
                v[nj][0] = acc[mi][nj][0] * iv0[mi]; v[nj][1] = acc[mi][nj][1] * iv0[mi];
                v[nj][2] = acc[mi][nj][2] * iv1[mi]; v[nj][3] = acc[mi][nj][3] * iv1[mi];
            }
            tile_store(stg, v, o2w + (size_t)mi * 262144 + kt * 128, l);
        }
        __syncthreads();
    }

    #pragma unroll
    for (int mi = 0; mi < 2; ++mi) {
        rlo[mi] += __shfl_xor_sync(0xffffffffu, rlo[mi], 1);
        rlo[mi] += __shfl_xor_sync(0xffffffffu, rlo[mi], 2);
        rhi[mi] += __shfl_xor_sync(0xffffffffu, rhi[mi], 1);
        rhi[mi] += __shfl_xor_sync(0xffffffffu, rhi[mi], 2);
        if ((l & 3) == 0) {
            atomicAdd(&rsf[wr * 32 + mi * 16 + (l >> 2)], rlo[mi]);
            atomicAdd(&rsf[wr * 32 + mi * 16 + (l >> 2) + 8], rhi[mi]);
        }
    }
    __syncthreads();
    if (tid < 128) rsf[tid] = 1.0f / rsf[tid];
    __syncthreads();

    float rv0[2], rv1[2];
    #pragma unroll
    for (int mi = 0; mi < 2; ++mi) {
        rv0[mi] = rsf[wr * 32 + mi * 16 + (l >> 2)];
        rv1[mi] = rsf[wr * 32 + mi * 16 + (l >> 2) + 8];
    }

    // ================= sweep 2 =================
    stageB<false>(sb, B0OFF, b, h, bh, 0, tid);
    CP_COMMIT();
    for (int kt = 0; kt < 8; ++kt) {
        if (kt < 7) { stageB<false>(sb, B0OFF + ((kt + 1) & 1) * BSZ, b, h, bh, (kt + 1) * 128, tid); CP_COMMIT(); CP_WAIT1(); }
        else CP_WAIT0();
        __syncthreads();
        const uint bufo = B0OFF + (kt & 1) * BSZ;

        float acc[2][4][4];
        #pragma unroll
        for (int mi = 0; mi < 2; ++mi)
            #pragma unroll
            for (int nj = 0; nj < 4; ++nj)
                #pragma unroll
                for (int e = 0; e < 4; ++e) acc[mi][nj][e] = 0.f;
        #pragma unroll
        for (int ks = 0; ks < 4; ++ks) {
            uint A0[4], A1[4], B0[4], B1[4];
            ldsm4(A0, qA + ks * 32);
            ldsm4(A1, qA + 2304 + ks * 32);
            ldsm4(B0, sb + bufo + kBrel + ks * 32);
            ldsm4(B1, sb + bufo + kBrel + 2304 + ks * 32);
            mma168(acc[0][0], A0, B0[0], B0[2]); mma168(acc[0][1], A0, B0[1], B0[3]);
            mma168(acc[0][2], A0, B1[0], B1[2]); mma168(acc[0][3], A0, B1[1], B1[3]);
            mma168(acc[1][0], A1, B0[0], B0[2]); mma168(acc[1][1], A1, B0[1], B0[3]);
            mma168(acc[1][2], A1, B1[0], B1[2]); mma168(acc[1][3], A1, B1[1], B1[3]);
        }
        #pragma unroll
        for (int mi = 0; mi < 2; ++mi) {
            float v[4][4];
            #pragma unroll
            for (int nj = 0; nj < 4; ++nj) {
                v[nj][0] = __expf(acc[mi][nj][0]) * rv0[mi];
                v[nj][1] = __expf(acc[mi][nj][1]) * rv0[mi];
                v[nj][2] = __expf(acc[mi][nj][2]) * rv1[mi];
                v[nj][3] = __expf(acc[mi][nj][3]) * rv1[mi];
            }
            tile_store(stg, v, o1w + (size_t)mi * 262144 + kt * 128, l);
        }
        __syncthreads();
    }
}

// =====================================================================
extern "C" void kernel_launch(void* const* d_in, const int* in_sizes, int n_in,
                              void* d_out, int out_size) {
    const float* q  = (const float*)d_in[0];
    const float* k  = (const float*)d_in[1];
    const float* Wq = (const float*)d_in[2];
    const float* bq = (const float*)d_in[3];
    const float* Wk = (const float*)d_in[4];
    const float* bk = (const float*)d_in[5];
    float* out = (float*)d_out;

    cudaFuncSetAttribute(hedgehog_prep3, cudaFuncAttributeMaxDynamicSharedMemorySize, PREP_SMEM);
    cudaFuncSetAttribute(hedgehog_main, cudaFuncAttributeMaxDynamicSharedMemorySize, SMEMB);
    hedgehog_prep3<<<1024, 256, PREP_SMEM>>>(q, k, Wq, bq, Wk, bk);
    hedgehog_ksum<<<64, 256>>>();
    hedgehog_main<<<dim3(8, 64), 512, SMEMB>>>(out);
}

// round 9
// speedup vs baseline: 1.1360x; 1.1360x over previous
#include <cuda_runtime.h>
#include <cuda_fp16.h>
#include <cstdint>

#define MAPSZ 67108864u
typedef unsigned uint;
typedef unsigned long long u64;

// ---------------- device scratch: single fp16 planes ----------------
__device__ __half g_q16[4194304];     // q * 0.125, [b][t][h][d]
__device__ __half g_k16[4194304];     // k,        [b][t][h][d]
__device__ __half g_pq16[8388608];    // phi_q,    [bh][t][128]
__device__ __half g_pk16[8388608];    // phi_k,    [bh][t][128]
__device__ float  g_sk[64 * 128];     // column sums of phi_k per bh

// ---------------- helpers ----------------
__device__ __forceinline__ float frcp(float x) { float r; asm("rcp.approx.ftz.f32 %0,%1;" : "=f"(r) : "f"(x)); return r; }
__device__ __forceinline__ uint packh(float hi, float lo) { uint r; asm("cvt.rn.f16x2.f32 %0,%1,%2;" : "=r"(r) : "f"(hi), "f"(lo)); return r; }
__device__ __forceinline__ uint smem_u32(const void* p) {
    uint a; asm("{ .reg .u64 t; cvta.to.shared.u64 t,%1; cvt.u32.u64 %0,t; }" : "=r"(a) : "l"(p)); return a;
}
__device__ __forceinline__ void cp16(uint dst, const void* src) {
    asm volatile("cp.async.cg.shared.global [%0],[%1],16;" :: "r"(dst), "l"(src));
}
#define CP_COMMIT() asm volatile("cp.async.commit_group;")
#define CP_WAIT0()  asm volatile("cp.async.wait_group 0;")
#define CP_WAIT1()  asm volatile("cp.async.wait_group 1;")

__device__ __forceinline__ void ldsm4(uint* r, uint addr) {
    asm volatile("ldmatrix.sync.aligned.m8n8.x4.shared.b16 {%0,%1,%2,%3},[%4];"
                 : "=r"(r[0]), "=r"(r[1]), "=r"(r[2]), "=r"(r[3]) : "r"(addr));
}
__device__ __forceinline__ void mma168(float* c, const uint* a, uint b0, uint b1) {
    asm volatile("mma.sync.aligned.m16n8k16.row.col.f32.f16.f16.f32 "
                 "{%0,%1,%2,%3},{%4,%5,%6,%7},{%8,%9},{%0,%1,%2,%3};"
                 : "+f"(c[0]), "+f"(c[1]), "+f"(c[2]), "+f"(c[3])
                 : "r"(a[0]), "r"(a[1]), "r"(a[2]), "r"(a[3]), "r"(b0), "r"(b1));
}
__device__ __forceinline__ void stcs2(float* p, float a, float b) {
    asm volatile("st.global.cs.v2.f32 [%0],{%1,%2};" :: "l"(p), "f"(a), "f"(b) : "memory");
}

// =====================================================================
// Kernel 1: feature maps via hi/lo fp16 mma. grid 1024; 256 threads.
// (unchanged from R7 — 47us, proven)
// =====================================================================
#define PXH 0u
#define PXL 18432u
#define PWH 36864u
#define PWL 46080u
#define PREP_SMEM 55296

__global__ __launch_bounds__(256) void hedgehog_prep3(
    const float* __restrict__ q, const float* __restrict__ k,
    const float* __restrict__ Wq, const float* __restrict__ bq,
    const float* __restrict__ Wk, const float* __restrict__ bk)
{
    extern __shared__ __align__(16) char sm[];
    const uint sb = smem_u32(sm);
    const int tid = threadIdx.x, bid = blockIdx.x;
    const int w = tid >> 5, l = tid & 31;
    const int tensor = bid >> 9, rem = bid & 511;
    const int b = rem >> 7, h = (rem >> 3) & 15, t0 = (rem & 7) * 128;
    const float* W  = tensor ? Wk : Wq;
    const float* bi = tensor ? bk : bq;
    const float* x  = tensor ? k  : q;
    const float sc  = tensor ? 1.0f : 0.125f;
    __half* xout = tensor ? g_k16 : g_q16;
    __half* pout = tensor ? g_pk16 : g_pq16;

    #pragma unroll
    for (int i = 0; i < 16; ++i) {
        int idx = i * 256 + tid;
        int e = idx >> 6, d = idx & 63;
        float v = W[idx];
        __half hv = __float2half_rn(v);
        *(__half*)(sm + PWH + (e * 72 + d) * 2) = hv;
        *(__half*)(sm + PWL + (e * 72 + d) * 2) = __float2half_rn(v - __half2float(hv));
    }
    {
        const int row = tid >> 1, hf = tid & 1;
        const size_t xi = ((size_t)((b * 1024 + t0 + row) * 16 + h)) * 64 + hf * 32;
        const float4* xp = (const float4*)(x + xi);
        uint* xw = (uint*)(xout + xi);
        uint* XH = (uint*)(sm + PXH + (row * 72 + hf * 32) * 2);
        uint* XL = (uint*)(sm + PXL + (row * 72 + hf * 32) * 2);
        #pragma unroll
        for (int i = 0; i < 8; ++i) {
            float4 v = xp[i];
            xw[i * 2]     = packh(v.y * sc, v.x * sc);
            xw[i * 2 + 1] = packh(v.w * sc, v.z * sc);
            uint h0 = packh(v.y, v.x), h1 = packh(v.w, v.z);
            XH[i * 2] = h0; XH[i * 2 + 1] = h1;
            float2 r0 = __half22float2(*(__half2*)&h0), r1 = __half22float2(*(__half2*)&h1);
            XL[i * 2]     = packh(v.y - r0.y, v.x - r0.x);
            XL[i * 2 + 1] = packh(v.w - r1.y, v.z - r1.x);
        }
    }
    __syncthreads();

    const uint aK  = (uint)(l >> 4) * 16;
    const uint aH  = sb + PXH + (w * 16 + (l & 15)) * 144u + aK;
    const uint aL  = sb + PXL + (w * 16 + (l & 15)) * 144u + aK;
    const uint bRow = (uint)((l & 7) + ((l >> 3) & 1) * 8);

    float acc[8][4];
    #pragma unroll
    for (int nj = 0; nj < 8; ++nj)
        #pragma unroll
        for (int e = 0; e < 4; ++e) acc[nj][e] = 0.f;

    #pragma unroll
    for (int ks = 0; ks < 4; ++ks) {
        uint AH[4], AL[4];
        ldsm4(AH, aH + ks * 32);
        ldsm4(AL, aL + ks * 32);
        #pragma unroll
        for (int g = 0; g < 4; ++g) {
            uint BH[4], BL[4];
            const uint bo = (g * 16 + bRow) * 144u + aK + ks * 32;
            ldsm4(BH, sb + PWH + bo);
            ldsm4(BL, sb + PWL + bo);
            mma168(acc[g * 2],     AH, BH[0], BH[2]);
            mma168(acc[g * 2],     AL, BH[0], BH[2]);
            mma168(acc[g * 2],     AH, BL[0], BL[2]);
            mma168(acc[g * 2 + 1], AH, BH[1], BH[3]);
            mma168(acc[g * 2 + 1], AL, BH[1], BH[3]);
            mma168(acc[g * 2 + 1], AH, BL[1], BL[3]);
        }
    }

    const float* bb = bi;
    const int r0 = w * 16 + (l >> 2), r1 = r0 + 8;
    uint* p0 = (uint*)(pout + ((size_t)(b * 16 + h) * 1024 + t0 + r0) * 128);
    uint* p1 = (uint*)(pout + ((size_t)(b * 16 + h) * 1024 + t0 + r1) * 128);
    #pragma unroll
    for (int nj = 0; nj < 8; ++nj) {
        const int c = nj * 8 + (l & 3) * 2;
        const float b0 = bb[c], b1 = bb[c + 1];
        float e0 = __expf(acc[nj][0] + b0), e1 = __expf(acc[nj][1] + b1);
        float e2 = __expf(acc[nj][2] + b0), e3 = __expf(acc[nj][3] + b1);
        const int ci = nj * 4 + (l & 3);
        p0[ci]      = packh(e1, e0);
        p0[32 + ci] = packh(frcp(e1), frcp(e0));
        p1[ci]      = packh(e3, e2);
        p1[32 + ci] = packh(frcp(e3), frcp(e2));
    }
}

// =====================================================================
// Kernel 1b: column sums of phi_k. grid 64, 256 threads (coalesced).
// =====================================================================
__global__ __launch_bounds__(256) void hedgehog_ksum() {
    __shared__ float red[4][128];
    const int bh = blockIdx.x, tid = threadIdx.x;
    const int c2 = tid & 63, rg = tid >> 6;
    const __half2* src = (const __half2*)(g_pk16 + (size_t)bh * 131072) + c2;
    float sx = 0.f, sy = 0.f;
    #pragma unroll 8
    for (int t = rg; t < 1024; t += 4) {
        float2 v = __half22float2(src[(size_t)t * 64]);
        sx += v.x; sy += v.y;
    }
    red[rg][2 * c2] = sx; red[rg][2 * c2 + 1] = sy;
    __syncthreads();
    if (tid < 128)
        g_sk[bh * 128 + tid] = (red[0][tid] + red[1][tid]) + (red[2][tid] + red[3][tid]);
}

// =====================================================================
// Kernel 2: fp16 mma.sync main, 2 CTAs/SM.
// grid (16,64), 256 threads (8 warps = 2 wr x 4 wc). q-tile 64 rows,
// k-tiles 64 rows. smem 79KB. Hoisted map1 A-fragments.
// =====================================================================
#define QOFF  0u
#define PQOFF 9216u
#define B0OFF 26624u
#define BSZ   26624u
#define SKOFF 79872u
#define IVOFF 80384u
#define RSOFF 80640u
#define SMEMB 80896

template<bool WITH_PK>
__device__ __forceinline__ void stageB(uint sb, uint bufo, int b, int h, int bh, int kr, int tid) {
    #pragma unroll
    for (int i = 0; i < 2; ++i) {                   // K tile: 64 x 64h
        int idx = i * 256 + tid;
        int r = idx >> 3, c = idx & 7;
        cp16(sb + bufo + r * 144u + c * 16u,
             g_k16 + ((size_t)((b * 1024 + kr + r) * 16 + h)) * 64 + c * 8);
    }
    if (WITH_PK) {
        #pragma unroll
        for (int i = 0; i < 4; ++i) {               // PK tile: 64 x 128h
            int idx = i * 256 + tid;
            int r = idx >> 4, c = idx & 15;
            cp16(sb + bufo + 9216u + r * 272u + c * 16u,
                 g_pk16 + ((size_t)bh * 1024 + kr + r) * 128 + c * 8);
        }
    }
}

__global__ __launch_bounds__(256, 2) void hedgehog_main(float* __restrict__ out)
{
    extern __shared__ __align__(16) char sm[];
    const uint sb = smem_u32(sm);
    const int tid = threadIdx.x, w = tid >> 5, l = tid & 31;
    const int wr = w >> 2, wc = w & 3;
    const int qt = blockIdx.x, bh = blockIdx.y;
    const int b = bh >> 4, h = bh & 15, t0 = qt * 64;
    float* skf = (float*)(sm + SKOFF);
    float* ivf = (float*)(sm + IVOFF);
    float* rsf = (float*)(sm + RSOFF);

    // ---- prologue staging (one group: Q, PQ, B0) ----
    #pragma unroll
    for (int i = 0; i < 2; ++i) {
        int idx = i * 256 + tid;
        int r = idx >> 3, c = idx & 7;
        cp16(sb + QOFF + r * 144u + c * 16u,
             g_q16 + ((size_t)((b * 1024 + t0 + r) * 16 + h)) * 64 + c * 8);
    }
    #pragma unroll
    for (int i = 0; i < 4; ++i) {
        int idx = i * 256 + tid;
        int r = idx >> 4, c = idx & 15;
        cp16(sb + PQOFF + r * 272u + c * 16u,
             g_pq16 + ((size_t)bh * 1024 + t0 + r) * 128 + c * 8);
    }
    stageB<true>(sb, B0OFF, b, h, bh, 0, tid);
    CP_COMMIT();

    if (tid < 128) skf[tid] = g_sk[bh * 128 + tid];
    if (tid < 64)  rsf[tid] = 0.f;
    CP_WAIT0();
    __syncthreads();

    if (tid < 64) {                                  // inv2 per q-row
        const uint* pr = (const uint*)(sm + PQOFF + tid * 272);
        float s = 0.f;
        #pragma unroll 16
        for (int i = 0; i < 64; ++i) {
            float2 v = __half22float2(*(const __half2*)(pr + i));
            s = fmaf(v.x, skf[2 * i], s);
            s = fmaf(v.y, skf[2 * i + 1], s);
        }
        ivf[tid] = 1.0f / s;
    }
    __syncthreads();

    // ---- addressing + hoisted map1 A-fragments ----
    const uint aK = (uint)(l >> 4) * 16;
    const uint qA = sb + QOFF  + (wr * 32 + (l & 15)) * 144u + aK;
    const uint pA = sb + PQOFF + (wr * 32 + (l & 15)) * 272u + aK;
    const uint bRow = (uint)((l & 7) + ((l >> 3) & 1) * 8);
    const uint kBrel = (wc * 16 + bRow) * 144u + aK;
    const uint pBrel = 9216u + (wc * 16 + bRow) * 272u + aK;

    uint QA0[4][4], QA1[4][4];
    #pragma unroll
    for (int ks = 0; ks < 4; ++ks) {
        ldsm4(QA0[ks], qA + ks * 32);
        ldsm4(QA1[ks], qA + 2304 + ks * 32);
    }

    float* o1 = out + ((size_t)((b * 1024 + t0 + wr * 32 + (l >> 2)) * 16 + h)) * 1024
                + wc * 16 + 2 * (l & 3);
    float* o2 = o1 + MAPSZ;

    float iv0[2], iv1[2];
    #pragma unroll
    for (int mi = 0; mi < 2; ++mi) {
        iv0[mi] = ivf[wr * 32 + mi * 16 + (l >> 2)];
        iv1[mi] = ivf[wr * 32 + mi * 16 + (l >> 2) + 8];
    }
    float rlo[2] = {0.f, 0.f}, rhi[2] = {0.f, 0.f};

    // ================= sweep 1 =================
    for (int kt = 0; kt < 16; ++kt) {
        if (kt < 15) { stageB<true>(sb, B0OFF + ((kt + 1) & 1) * BSZ, b, h, bh, (kt + 1) * 64, tid); CP_COMMIT(); CP_WAIT1(); }
        else CP_WAIT0();
        __syncthreads();
        const uint bufo = B0OFF + (kt & 1) * BSZ;

        // map1: scores (K=64), rowsums only
        float a1[2][2][4];
        #pragma unroll
        for (int mi = 0; mi < 2; ++mi)
            #pragma unroll
            for (int nj = 0; nj < 2; ++nj)
                #pragma unroll
                for (int e = 0; e < 4; ++e) a1[mi][nj][e] = 0.f;
        #pragma unroll
        for (int ks = 0; ks < 4; ++ks) {
            uint B[4];
            ldsm4(B, sb + bufo + kBrel + ks * 32);
            mma168(a1[0][0], QA0[ks], B[0], B[2]); mma168(a1[0][1], QA0[ks], B[1], B[3]);
            mma168(a1[1][0], QA1[ks], B[0], B[2]); mma168(a1[1][1], QA1[ks], B[1], B[3]);
        }
        #pragma unroll
        for (int mi = 0; mi < 2; ++mi)
            #pragma unroll
            for (int nj = 0; nj < 2; ++nj) {
                rlo[mi] += __expf(a1[mi][nj][0]) + __expf(a1[mi][nj][1]);
                rhi[mi] += __expf(a1[mi][nj][2]) + __expf(a1[mi][nj][3]);
            }

        // map2: phi (K=128), normalized, stored
        float a2[2][2][4];
        #pragma unroll
        for (int mi = 0; mi < 2; ++mi)
            #pragma unroll
            for (int nj = 0; nj < 2; ++nj)
                #pragma unroll
                for (int e = 0; e < 4; ++e) a2[mi][nj][e] = 0.f;
        #pragma unroll
        for (int ks = 0; ks < 8; ++ks) {
            uint A0[4], A1[4], B[4];
            ldsm4(A0, pA + ks * 32);
            ldsm4(A1, pA + 4352 + ks * 32);
            ldsm4(B, sb + bufo + pBrel + ks * 32);
            mma168(a2[0][0], A0, B[0], B[2]); mma168(a2[0][1], A0, B[1], B[3]);
            mma168(a2[1][0], A1, B[0], B[2]); mma168(a2[1][1], A1, B[1], B[3]);
        }
        #pragma unroll
        for (int mi = 0; mi < 2; ++mi)
            #pragma unroll
            for (int nj = 0; nj < 2; ++nj) {
                float* p = o2 + (size_t)mi * 262144 + kt * 64 + nj * 8;
                stcs2(p,             a2[mi][nj][0] * iv0[mi], a2[mi][nj][1] * iv0[mi]);
                stcs2(p + 8 * 16384, a2[mi][nj][2] * iv1[mi], a2[mi][nj][3] * iv1[mi]);
            }
        __syncthreads();
    }

    // ---- rowsum reduce -> rs ----
    #pragma unroll
    for (int mi = 0; mi < 2; ++mi) {
        rlo[mi] += __shfl_xor_sync(0xffffffffu, rlo[mi], 1);
        rlo[mi] += __shfl_xor_sync(0xffffffffu, rlo[mi], 2);
        rhi[mi] += __shfl_xor_sync(0xffffffffu, rhi[mi], 1);
        rhi[mi] += __shfl_xor_sync(0xffffffffu, rhi[mi], 2);
        if ((l & 3) == 0) {
            atomicAdd(&rsf[wr * 32 + mi * 16 + (l >> 2)], rlo[mi]);
            atomicAdd(&rsf[wr * 32 + mi * 16 + (l >> 2) + 8], rhi[mi]);
        }
    }
    __syncthreads();
    if (tid < 64) rsf[tid] = 1.0f / rsf[tid];
    __syncthreads();

    float rv0[2], rv1[2];
    #pragma unroll
    for (int mi = 0; mi < 2; ++mi) {
        rv0[mi] = rsf[wr * 32 + mi * 16 + (l >> 2)];
        rv1[mi] = rsf[wr * 32 + mi * 16 + (l >> 2) + 8];
    }

    // ================= sweep 2: map1 recompute + store =================
    stageB<false>(sb, B0OFF, b, h, bh, 0, tid);
    CP_COMMIT();
    for (int kt = 0; kt < 16; ++kt) {
        if (kt < 15) { stageB<false>(sb, B0OFF + ((kt + 1) & 1) * BSZ, b, h, bh, (kt + 1) * 64, tid); CP_COMMIT(); CP_WAIT1(); }
        else CP_WAIT0();
        __syncthreads();
        const uint bufo = B0OFF + (kt & 1) * BSZ;

        float a1[2][2][4];
        #pragma unroll
        for (int mi = 0; mi < 2; ++mi)
            #pragma unroll
            for (int nj = 0; nj < 2; ++nj)
                #pragma unroll
                for (int e = 0; e < 4; ++e) a1[mi][nj][e] = 0.f;
        #pragma unroll
        for (int ks = 0; ks < 4; ++ks) {
            uint B[4];
            ldsm4(B, sb + bufo + kBrel + ks * 32);
            mma168(a1[0][0], QA0[ks], B[0], B[2]); mma168(a1[0][1], QA0[ks], B[1], B[3]);
            mma168(a1[1][0], QA1[ks], B[0], B[2]); mma168(a1[1][1], QA1[ks], B[1], B[3]);
        }
        #pragma unroll
        for (int mi = 0; mi < 2; ++mi)
            #pragma unroll
            for (int nj = 0; nj < 2; ++nj) {
                float* p = o1 + (size_t)mi * 262144 + kt * 64 + nj * 8;
                stcs2(p,             __expf(a1[mi][nj][0]) * rv0[mi], __expf(a1[mi][nj][1]) * rv0[mi]);
                stcs2(p + 8 * 16384, __expf(a1[mi][nj][2]) * rv1[mi], __expf(a1[mi][nj][3]) * rv1[mi]);
            }
        __syncthreads();
    }
}

// =====================================================================
extern "C" void kernel_launch(void* const* d_in, const int* in_sizes, int n_in,
                              void* d_out, int out_size) {
    const float* q  = (const float*)d_in[0];
    const float* k  = (const float*)d_in[1];
    const float* Wq = (const float*)d_in[2];
    const float* bq = (const float*)d_in[3];
    const float* Wk = (const float*)d_in[4];
    const float* bk = (const float*)d_in[5];
    float* out = (float*)d_out;

    cudaFuncSetAttribute(hedgehog_prep3, cudaFuncAttributeMaxDynamicSharedMemorySize, PREP_SMEM);
    cudaFuncSetAttribute(hedgehog_main, cudaFuncAttributeMaxDynamicSharedMemorySize, SMEMB);
    hedgehog_prep3<<<1024, 256, PREP_SMEM>>>(q, k, Wq, bq, Wk, bk);
    hedgehog_ksum<<<64, 256>>>();
    hedgehog_main<<<dim3(16, 64), 256, SMEMB>>>(out);
}